// round 9
// baseline (speedup 1.0000x reference)
#include <cuda_runtime.h>
#include <cuda_bf16.h>
#include <math.h>

// SimDiff: right[f,i] = cos(x[f,i], x[f+iv, i+1])      (i < tpf-1)
//          down [f,i] = cos(x[f,i], x[f+iv, i+width])  (i < tpf-width)
// else -1. Output: [right | down], each frames*tpf f32.
//
// Model: chip LTS cap ~6300 B/cyc = ~42.5 B/cyc/SM — R2/R5 pinned there at
// 3.0x volume (489MB). R8 proved chain-carry reduces volume to 2.25x but the
// 36-reg anchor killed occupancy. This round: SMEM-CARRIED CHAIN. Each warp
// owns a private 4.6KB smem anchor buffer (zero barriers: every smem word is
// touched by exactly one lane). Per chain step, per float4 chunk:
//   LDG b (next-anchor), LDG c (down-target), LDS a, FMAs, STS b -> a-slot.
// LDS/STS use the smem crossbar, not LTS. Registers ~56 -> 32+ warps/SM
// restores R2's in-flight bytes at 0.75x the L2 volume.

#define EPSN 1e-8f
#define SEG 4

template <int NPL>  // D = NPL * 128 floats
__global__ void __launch_bounds__(256, 4) simdiff_smemcarry_kernel(
    const float* __restrict__ x,
    const int* __restrict__ p_frames,
    const int* __restrict__ p_height,
    const int* __restrict__ p_width,
    const int* __restrict__ p_interval,
    float* __restrict__ out,
    int total)
{
    extern __shared__ float4 abuf[];   // [8 warps][NPL*32] float4

    const int width  = *p_width;
    const int height = *p_height;
    const int frames = *p_frames;
    const int iv     = *p_interval;
    const int tpf    = width * height;

    // Chains step (f += iv, i += 1); starts: f0 < iv (any i0) or i0 == 0.
    const int nch_a = iv * tpf;
    const int nch_b = frames > iv ? frames - iv : 0;
    const int maxL  = min((frames + iv - 1) / iv, tpf);
    const int nsegper = (maxL + SEG - 1) / SEG;
    const long nseg = (long)(nch_a + nch_b) * nsegper;

    const int lane = threadIdx.x & 31;
    const int wib  = threadIdx.x >> 5;  // warp in block
    const long wstride = (long)gridDim.x * (blockDim.x >> 5);
    const long w0 = ((long)blockIdx.x * blockDim.x + threadIdx.x) >> 5;

    float4* __restrict__ buf = abuf + wib * (NPL * 32) + lane;

    float* __restrict__ outR = out;
    float* __restrict__ outD = out + total;
    const float4* __restrict__ x4 = reinterpret_cast<const float4*>(x);
    const int vs   = NPL * 32;          // float4 per token vector
    const int dtok = iv * tpf + 1;      // chain step in tokens
    const int ctok = iv * tpf + width;  // down-target offset in tokens

    for (long g = w0; g < nseg; g += wstride) {
        const int chain = (int)(g / nsegper);
        const int seg   = (int)(g - (long)chain * nsegper);

        int f0, i0;
        if (chain < nch_a) { f0 = chain % iv; i0 = chain / iv; }
        else               { f0 = iv + (chain - nch_a); i0 = 0; }
        if (f0 >= frames || i0 >= tpf) continue;

        const int L  = min((frames - f0 + iv - 1) / iv, tpf - i0);
        const int k0 = seg * SEG;
        if (k0 >= L) continue;
        const int ns = min(SEG, L - k0);

        int fA = f0 + k0 * iv;
        int iA = i0 + k0;
        int t  = fA * tpf + iA;

        // Prologue: anchor -> smem buffer; accumulate + reduce |a|^2.
        {
            const float4* __restrict__ ap = x4 + (long)t * vs + lane;
            float na0 = 0.0f;
#pragma unroll
            for (int ch = 0; ch < NPL; ch++) {
                const float4 v = ap[32 * ch];
                buf[32 * ch] = v;
                na0 = fmaf(v.x, v.x, na0); na0 = fmaf(v.y, v.y, na0);
                na0 = fmaf(v.z, v.z, na0); na0 = fmaf(v.w, v.w, na0);
            }
#pragma unroll
            for (int off = 16; off > 0; off >>= 1)
                na0 += __shfl_xor_sync(0xFFFFFFFFu, na0, off);
            // carried anchor norm
            float na = na0;

            for (int k = 0; k < ns; k++) {
                const bool fv = (fA + iv) < frames;
                const bool vr = fv && (iA + 1 < tpf);
                const bool vd = fv && (iA < tpf - width);
                const int tb = t + dtok;
                const int tc = t + ctok;
                // Clamp invalid targets to current anchor (in-bounds); the
                // outputs are forced to -1. vr false => last step of chain,
                // so the garbage carry is never consumed.
                const float4* __restrict__ bp =
                    x4 + (long)(vr ? tb : t) * vs + lane;
                const float4* __restrict__ cp =
                    x4 + (long)(vd ? tc : t) * vs + lane;

                float d1 = 0.f, n1 = 0.f, d2 = 0.f, n2 = 0.f;
#pragma unroll
                for (int ch = 0; ch < NPL; ch++) {
                    const float4 b = bp[32 * ch];
                    const float4 c = cp[32 * ch];
                    const float4 a = buf[32 * ch];
                    d1 = fmaf(a.x, b.x, d1); d1 = fmaf(a.y, b.y, d1);
                    d1 = fmaf(a.z, b.z, d1); d1 = fmaf(a.w, b.w, d1);
                    n1 = fmaf(b.x, b.x, n1); n1 = fmaf(b.y, b.y, n1);
                    n1 = fmaf(b.z, b.z, n1); n1 = fmaf(b.w, b.w, n1);
                    d2 = fmaf(a.x, c.x, d2); d2 = fmaf(a.y, c.y, d2);
                    d2 = fmaf(a.z, c.z, d2); d2 = fmaf(a.w, c.w, d2);
                    n2 = fmaf(c.x, c.x, n2); n2 = fmaf(c.y, c.y, n2);
                    n2 = fmaf(c.z, c.z, n2); n2 = fmaf(c.w, c.w, n2);
                    buf[32 * ch] = b;   // carry: target becomes next anchor
                }
#pragma unroll
                for (int off = 16; off > 0; off >>= 1) {
                    d1 += __shfl_xor_sync(0xFFFFFFFFu, d1, off);
                    n1 += __shfl_xor_sync(0xFFFFFFFFu, n1, off);
                    d2 += __shfl_xor_sync(0xFFFFFFFFu, d2, off);
                    n2 += __shfl_xor_sync(0xFFFFFFFFu, n2, off);
                }
                if (lane == 0) {
                    const float nA = fmaxf(sqrtf(na), EPSN);
                    outR[t] = vr ? d1 / (nA * fmaxf(sqrtf(n1), EPSN)) : -1.0f;
                    outD[t] = vd ? d2 / (nA * fmaxf(sqrtf(n2), EPSN)) : -1.0f;
                }
                na = n1;            // reduced |b|^2 = next anchor's norm
                t = tb; fA += iv; iA += 1;
            }
        }
    }
}

// Generic fallback for arbitrary D (scalar loads, one warp per token).
__global__ void __launch_bounds__(256) simdiff_generic_kernel(
    const float* __restrict__ x,
    const int* __restrict__ p_frames,
    const int* __restrict__ p_height,
    const int* __restrict__ p_width,
    const int* __restrict__ p_interval,
    float* __restrict__ out,
    int total, int D)
{
    const int gwarp = (blockIdx.x * blockDim.x + threadIdx.x) >> 5;
    const int lane  = threadIdx.x & 31;
    if (gwarp >= total) return;

    const int width    = *p_width;
    const int height   = *p_height;
    const int frames   = *p_frames;
    const int interval = *p_interval;
    const int tpf      = width * height;

    const int f = gwarp / tpf;
    const int i = gwarp - f * tpf;

    float* __restrict__ outR = out;
    float* __restrict__ outD = out + total;

    const bool vf = (f + interval) < frames;
    if (!vf) {
        if (lane == 0) { outR[gwarp] = -1.0f; outD[gwarp] = -1.0f; }
        return;
    }
    const bool vr = (i < tpf - 1);
    const bool vd = (i < tpf - width);

    const size_t bframe = (size_t)(f + interval) * tpf + i;
    const size_t i1 = vr ? (bframe + 1)     : bframe;
    const size_t i2 = vd ? (bframe + width) : bframe;

    const float* a = x + (size_t)gwarp * D;
    const float* b = x + i1 * D;
    const float* c = x + i2 * D;

    float na = 0.0f, d1 = 0.0f, n1 = 0.0f, d2 = 0.0f, n2 = 0.0f;
    for (int k = lane; k < D; k += 32) {
        float av = a[k], bv = b[k], cv = c[k];
        na = fmaf(av, av, na);
        d1 = fmaf(av, bv, d1); n1 = fmaf(bv, bv, n1);
        d2 = fmaf(av, cv, d2); n2 = fmaf(cv, cv, n2);
    }

#pragma unroll
    for (int off = 16; off > 0; off >>= 1) {
        na += __shfl_xor_sync(0xFFFFFFFFu, na, off);
        d1 += __shfl_xor_sync(0xFFFFFFFFu, d1, off);
        n1 += __shfl_xor_sync(0xFFFFFFFFu, n1, off);
        d2 += __shfl_xor_sync(0xFFFFFFFFu, d2, off);
        n2 += __shfl_xor_sync(0xFFFFFFFFu, n2, off);
    }

    if (lane == 0) {
        const float nA = fmaxf(sqrtf(na), EPSN);
        outR[gwarp] = vr ? d1 / (nA * fmaxf(sqrtf(n1), EPSN)) : -1.0f;
        outD[gwarp] = vd ? d2 / (nA * fmaxf(sqrtf(n2), EPSN)) : -1.0f;
    }
}

extern "C" void kernel_launch(void* const* d_in, const int* in_sizes, int n_in,
                              void* d_out, int out_size) {
    const float* x        = (const float*)d_in[0];
    const int* p_frames   = (const int*)d_in[1];
    const int* p_height   = (const int*)d_in[2];
    const int* p_width    = (const int*)d_in[3];
    const int* p_interval = (const int*)d_in[4];
    float* out = (float*)d_out;

    const int total = out_size / 2;            // frames * tpf
    const int D     = in_sizes[0] / total;     // hidden dim

    if (D == 1152 || D == 1024 || D == 1280) {
        // 8 warps/CTA x SEG tokens/warp; grid-stride covers chain-edge
        // extras, surplus warps exit immediately.
        const int blocks = total / (8 * SEG) + 256;
        const int smem = 8 * (D / 128) * 32 * 16;   // 8 warps * NPL*32 float4
        if (D == 1152) {
            simdiff_smemcarry_kernel<9><<<blocks, 256, smem>>>(
                x, p_frames, p_height, p_width, p_interval, out, total);
        } else if (D == 1024) {
            simdiff_smemcarry_kernel<8><<<blocks, 256, smem>>>(
                x, p_frames, p_height, p_width, p_interval, out, total);
        } else {
            simdiff_smemcarry_kernel<10><<<blocks, 256, smem>>>(
                x, p_frames, p_height, p_width, p_interval, out, total);
        }
    } else {
        const int blocks = (total + 7) / 8;
        simdiff_generic_kernel<<<blocks, 256>>>(
            x, p_frames, p_height, p_width, p_interval, out, total, D);
    }
}

// round 10
// speedup vs baseline: 1.5479x; 1.5479x over previous
#include <cuda_runtime.h>
#include <cuda_bf16.h>
#include <math.h>

// SimDiff: right[f,i] = cos(x[f,i], x[f+iv, i+1])      (i < tpf-1)
//          down [f,i] = cos(x[f,i], x[f+iv, i+width])  (i < tpf-width)
// else -1. Output: [right | down], each frames*tpf f32.
//
// R2's per-warp shape (independent 3-stream dot product, ~40 regs) is the
// only structure that has hit the chip LTS cap (~12.2 TB/s). This kernel
// keeps that body UNCHANGED and gets L2-traffic reduction for free via warp
// CO-SCHEDULING: a CTA's 8 warps form a W=2 (chains) x L=4 (steps) tile of
// the diagonal lattice. Warp (j,k)'s right-target address == warp (j,k+1)'s
// anchor address, and both stream chunk ch at ~the same cycle -> the two
// LDG.128 to the same lines merge in L1tex / hit L1. Distinct lines per CTA
// = W(1+2L) = 18 for 24 streams -> 2.25x L2 volume, zero extra registers,
// zero barriers, zero serialization. Worst case degenerates to R2 exactly.

#define EPSN 1e-8f
#define CW 2   // chains per CTA
#define CL 4   // steps per CTA

template <int NPL>  // D = NPL * 128 floats
__global__ void __launch_bounds__(256, 6) simdiff_lattice_kernel(
    const float* __restrict__ x,
    const int* __restrict__ p_frames,
    const int* __restrict__ p_height,
    const int* __restrict__ p_width,
    const int* __restrict__ p_interval,
    float* __restrict__ out,
    int total)
{
    const int width  = *p_width;
    const int height = *p_height;
    const int frames = *p_frames;
    const int iv     = *p_interval;
    const int tpf    = width * height;
    const int D      = NPL * 128;

    // Diagonal chains: step (f += iv, i += 1). Starts: f0 < iv (any i0),
    // or i0 == 0 (f0 in [iv, frames)). Every token lies on exactly one chain.
    const int nch_a = iv * tpf;
    const int nch_b = frames > iv ? frames - iv : 0;
    const int nch   = nch_a + nch_b;
    const int maxL  = min((frames + iv - 1) / iv, tpf);

    const int ncb = (nch + CW - 1) / CW;    // chain blocks
    const int nsb = (maxL + CL - 1) / CL;   // step blocks
    const long ntile = (long)ncb * nsb;

    const int wib  = threadIdx.x >> 5;      // 0..7
    const int lane = threadIdx.x & 31;
    const int jj   = wib & (CW - 1);        // chain offset in tile
    const int kk   = wib >> 1;              // step offset in tile (CW==2)

    float* __restrict__ outR = out;
    float* __restrict__ outD = out + total;
    const int dtok = iv * tpf + 1;          // right-target token offset
    const int ctok = iv * tpf + width;      // down-target token offset

    for (long p = blockIdx.x; p < ntile; p += gridDim.x) {
        const int cb = (int)(p % ncb);
        const int sb = (int)(p / ncb);

        const int ci = cb * CW + jj;
        if (ci >= nch) continue;

        int f0, i0;
        if (ci < nch_a) { f0 = ci % iv; i0 = ci / iv; }
        else            { f0 = iv + (ci - nch_a); i0 = 0; }
        if (f0 >= frames || i0 >= tpf) continue;

        const int Lc = min((frames - f0 + iv - 1) / iv, tpf - i0);
        const int s  = sb * CL + kk;
        if (s >= Lc) continue;

        const int fA = f0 + s * iv;
        const int iA = i0 + s;
        const int t  = fA * tpf + iA;

        const bool vf = (fA + iv) < frames;
        if (!vf) {
            if (lane == 0) { outR[t] = -1.0f; outD[t] = -1.0f; }
            continue;
        }
        const bool vr = (iA + 1 < tpf);
        const bool vd = (iA < tpf - width);

        // Clamp invalid targets to the anchor itself; outputs fixed below.
        const int tb = vr ? t + dtok : t;
        const int tc = vd ? t + ctok : t;

        const float4* __restrict__ a4 =
            reinterpret_cast<const float4*>(x + (size_t)t * D) + lane;
        const float4* __restrict__ b4 =
            reinterpret_cast<const float4*>(x + (size_t)tb * D) + lane;
        const float4* __restrict__ c4 =
            reinterpret_cast<const float4*>(x + (size_t)tc * D) + lane;

        float na = 0.0f, d1 = 0.0f, n1 = 0.0f, d2 = 0.0f, n2 = 0.0f;

        // R2 body: depth-1 software pipeline, 3 loads always in flight.
        float4 a = a4[0];
        float4 b = b4[0];
        float4 c = c4[0];
#pragma unroll
        for (int k = 0; k < NPL; k++) {
            float4 ac = a, bc = b, cc = c;
            if (k + 1 < NPL) {
                a = a4[32 * (k + 1)];
                b = b4[32 * (k + 1)];
                c = c4[32 * (k + 1)];
            }
            na = fmaf(ac.x, ac.x, na); na = fmaf(ac.y, ac.y, na);
            na = fmaf(ac.z, ac.z, na); na = fmaf(ac.w, ac.w, na);
            d1 = fmaf(ac.x, bc.x, d1); d1 = fmaf(ac.y, bc.y, d1);
            d1 = fmaf(ac.z, bc.z, d1); d1 = fmaf(ac.w, bc.w, d1);
            n1 = fmaf(bc.x, bc.x, n1); n1 = fmaf(bc.y, bc.y, n1);
            n1 = fmaf(bc.z, bc.z, n1); n1 = fmaf(bc.w, bc.w, n1);
            d2 = fmaf(ac.x, cc.x, d2); d2 = fmaf(ac.y, cc.y, d2);
            d2 = fmaf(ac.z, cc.z, d2); d2 = fmaf(ac.w, cc.w, d2);
            n2 = fmaf(cc.x, cc.x, n2); n2 = fmaf(cc.y, cc.y, n2);
            n2 = fmaf(cc.z, cc.z, n2); n2 = fmaf(cc.w, cc.w, n2);
        }

#pragma unroll
        for (int off = 16; off > 0; off >>= 1) {
            na += __shfl_xor_sync(0xFFFFFFFFu, na, off);
            d1 += __shfl_xor_sync(0xFFFFFFFFu, d1, off);
            n1 += __shfl_xor_sync(0xFFFFFFFFu, n1, off);
            d2 += __shfl_xor_sync(0xFFFFFFFFu, d2, off);
            n2 += __shfl_xor_sync(0xFFFFFFFFu, n2, off);
        }

        if (lane == 0) {
            const float nA = fmaxf(sqrtf(na), EPSN);
            outR[t] = vr ? d1 / (nA * fmaxf(sqrtf(n1), EPSN)) : -1.0f;
            outD[t] = vd ? d2 / (nA * fmaxf(sqrtf(n2), EPSN)) : -1.0f;
        }
    }
}

// Generic fallback for arbitrary D (scalar loads, one warp per token).
__global__ void __launch_bounds__(256) simdiff_generic_kernel(
    const float* __restrict__ x,
    const int* __restrict__ p_frames,
    const int* __restrict__ p_height,
    const int* __restrict__ p_width,
    const int* __restrict__ p_interval,
    float* __restrict__ out,
    int total, int D)
{
    const int gwarp = (blockIdx.x * blockDim.x + threadIdx.x) >> 5;
    const int lane  = threadIdx.x & 31;
    if (gwarp >= total) return;

    const int width    = *p_width;
    const int height   = *p_height;
    const int frames   = *p_frames;
    const int interval = *p_interval;
    const int tpf      = width * height;

    const int f = gwarp / tpf;
    const int i = gwarp - f * tpf;

    float* __restrict__ outR = out;
    float* __restrict__ outD = out + total;

    const bool vf = (f + interval) < frames;
    if (!vf) {
        if (lane == 0) { outR[gwarp] = -1.0f; outD[gwarp] = -1.0f; }
        return;
    }
    const bool vr = (i < tpf - 1);
    const bool vd = (i < tpf - width);

    const size_t bframe = (size_t)(f + interval) * tpf + i;
    const size_t i1 = vr ? (bframe + 1)     : bframe;
    const size_t i2 = vd ? (bframe + width) : bframe;

    const float* a = x + (size_t)gwarp * D;
    const float* b = x + i1 * D;
    const float* c = x + i2 * D;

    float na = 0.0f, d1 = 0.0f, n1 = 0.0f, d2 = 0.0f, n2 = 0.0f;
    for (int k = lane; k < D; k += 32) {
        float av = a[k], bv = b[k], cv = c[k];
        na = fmaf(av, av, na);
        d1 = fmaf(av, bv, d1); n1 = fmaf(bv, bv, n1);
        d2 = fmaf(av, cv, d2); n2 = fmaf(cv, cv, n2);
    }

#pragma unroll
    for (int off = 16; off > 0; off >>= 1) {
        na += __shfl_xor_sync(0xFFFFFFFFu, na, off);
        d1 += __shfl_xor_sync(0xFFFFFFFFu, d1, off);
        n1 += __shfl_xor_sync(0xFFFFFFFFu, n1, off);
        d2 += __shfl_xor_sync(0xFFFFFFFFu, d2, off);
        n2 += __shfl_xor_sync(0xFFFFFFFFu, n2, off);
    }

    if (lane == 0) {
        const float nA = fmaxf(sqrtf(na), EPSN);
        outR[gwarp] = vr ? d1 / (nA * fmaxf(sqrtf(n1), EPSN)) : -1.0f;
        outD[gwarp] = vd ? d2 / (nA * fmaxf(sqrtf(n2), EPSN)) : -1.0f;
    }
}

extern "C" void kernel_launch(void* const* d_in, const int* in_sizes, int n_in,
                              void* d_out, int out_size) {
    const float* x        = (const float*)d_in[0];
    const int* p_frames   = (const int*)d_in[1];
    const int* p_height   = (const int*)d_in[2];
    const int* p_width    = (const int*)d_in[3];
    const int* p_interval = (const int*)d_in[4];
    float* out = (float*)d_out;

    const int total = out_size / 2;            // frames * tpf
    const int D     = in_sizes[0] / total;     // hidden dim

    if (D == 1152 || D == 1024 || D == 1280) {
        // ~total/8 useful CTAs (8 warps each) + chain-edge padding; the
        // grid-stride loop covers any shape, surplus tiles exit fast.
        const int blocks = total / 8 + 1280;
        if (D == 1152) {
            simdiff_lattice_kernel<9><<<blocks, 256>>>(
                x, p_frames, p_height, p_width, p_interval, out, total);
        } else if (D == 1024) {
            simdiff_lattice_kernel<8><<<blocks, 256>>>(
                x, p_frames, p_height, p_width, p_interval, out, total);
        } else {
            simdiff_lattice_kernel<10><<<blocks, 256>>>(
                x, p_frames, p_height, p_width, p_interval, out, total);
        }
    } else {
        const int blocks = (total + 7) / 8;
        simdiff_generic_kernel<<<blocks, 256>>>(
            x, p_frames, p_height, p_width, p_interval, out, total, D);
    }
}